// round 7
// baseline (speedup 1.0000x reference)
#include <cuda_runtime.h>
#include <cuda_fp16.h>
#include <math.h>

#define NU 50000
#define NI 100000
#define NE 200000
#define NREL 32
#define DIM 64
#define NB 4096
#define EKG 2000000
#define EUI_HALF 1000000
#define NNODES 150000      // NU + NI

#define MAXLE NI           // upper bound on live entities
#define MAXLN (3 * NB)     // upper bound on live node rows = 12288

#define GEMM_BLOCKS ((NE + 255) / 256)          // 782
#define ZF4_AGGC  (MAXLE * DIM / 4)             // 1,600,000
#define ZF4_AGG2C (MAXLN * DIM / 4)             // 196,608
#define ZF4_TOTC  (ZF4_AGGC + ZF4_AGG2C)
#define CZBLOCKS  ((ZF4_TOTC + 2047) / 2048)    // 878

#define CKG_BLOCKS ((EKG + 255) / 256)          // 7813
#define CUI_BLOCKS ((EUI_HALF + 255) / 256)     // 3907
#define INIT_BLOCKS (GEMM_BLOCKS + CZBLOCKS + CKG_BLOCKS + 2 * CUI_BLOCKS)

#define EA_KG_BLOCKS 2048
#define EA_UI_BLOCKS 256
#define EB_BLOCKS 512

#define NFLAG_WORK (NI + 3 * NB)                // 112,288
#define DEGZ_F4 (MAXLE / 4)                     // 25,000
#define SF_THREADS (NFLAG_WORK + DEGZ_F4)
#define SF_BLOCKS ((SF_THREADS + 255) / 256)

#define QK_BLOCKS 512                           // NB*32/256
#define QCLEAN_I4 (NE / 4)                      // 50,000 int4 to zero remapE
#define QCLEAN_BLOCKS ((QCLEAN_I4 + 255) / 256) // 196
#define TAIL_I4 (NNODES / 4)                    // 37,500
#define TAIL_BLOCKS ((TAIL_I4 + 255) / 256)     // 147

// ---------------- scratch (static device globals; no allocation) ----------------
__device__ __half g_yh[NE * DIM];           // entity_emb @ W^T, fp16 (25.6MB, L2-resident)
__device__ float g_aggC[MAXLE * DIM];       // KG segment sum (dense live-entity rows)
__device__ float g_degC[MAXLE];             // KG in-degree (dense)
__device__ float g_itemkg[NI * DIM];        // per-item post-processed KG embedding
__device__ float g_agg2C[MAXLN * DIM];      // UI segment sum (dense live-node rows)
__device__ float g_gate[NREL * DIM];        // sigmoid(relation_emb)
__device__ int g_remapE[NE];                // 0 = dead, >=2 -> dense id + 2
__device__ int g_remapN[NNODES];
__device__ int g_nLiveE, g_nLiveN;
__device__ int g_nKG, g_nUIA, g_nUIB;
__device__ int   g_ksr[EKG];                // src | rel<<18
__device__ int   g_kdst[EKG];               // remapped dense dst
__device__ int   g_apk[EUI_HALF];           // rr | cc<<14  (A: row=item live id, col=user)
__device__ float g_aval[EUI_HALF];
__device__ int   g_bpk[EUI_HALF];           // rr | cc<<14  (B: row=user live id, col=item node)
__device__ float g_bval[EUI_HALF];

// vectorized no-return global atomic add (sm_90+)
__device__ __forceinline__ void red_add_v4(float* addr, float x, float y, float z, float w) {
    asm volatile("red.global.add.v4.f32 [%0], {%1,%2,%3,%4};"
                 :: "l"(addr), "f"(x), "f"(y), "f"(z), "f"(w)
                 : "memory");
}

__device__ __forceinline__ unsigned long long pack2(float a, float b) {
    unsigned long long r;
    asm("mov.b64 %0, {%1, %2};" : "=l"(r) : "f"(a), "f"(b));
    return r;
}
__device__ __forceinline__ void unpack2(unsigned long long v, float& a, float& b) {
    asm("mov.b64 {%0, %1}, %2;" : "=f"(a), "=f"(b) : "l"(v));
}
__device__ __forceinline__ void fma2(unsigned long long& d, unsigned long long a,
                                     unsigned long long b) {
    asm("fma.rn.f32x2 %0, %1, %2, %3;" : "=l"(d) : "l"(a), "l"(b), "l"(d));
}

// ---------------- K1: claim dense ids for live entities/nodes + zero degC ----------------
__global__ void set_flags_kernel(const int* __restrict__ i2e,
                                 const int* __restrict__ qu,
                                 const int* __restrict__ qi,
                                 const int* __restrict__ qn) {
    int t = blockIdx.x * blockDim.x + threadIdx.x;
    if (t < NI) {
        int e = __ldg(i2e + t);
        if (atomicCAS(&g_remapE[e], 0, 1) == 0)
            g_remapE[e] = 2 + atomicAdd(&g_nLiveE, 1);
    } else if (t < NFLAG_WORK) {
        int r = t - NI;
        int node;
        if (r < NB) node = __ldg(qu + r);
        else if (r < 2 * NB) node = NU + __ldg(qi + r - NB);
        else node = NU + __ldg(qn + r - 2 * NB);
        if (atomicCAS(&g_remapN[node], 0, 1) == 0)
            g_remapN[node] = 2 + atomicAdd(&g_nLiveN, 1);
    } else {
        int z = t - NFLAG_WORK;
        if (z < DEGZ_F4)
            reinterpret_cast<float4*>(g_degC)[z] = make_float4(0.f, 0.f, 0.f, 0.f);
    }
}

// ---------------- K2: fused GEMM(fp16 out) + zero + compaction + deg ----------------
__global__ void init_kernel(const float* __restrict__ x, const float* __restrict__ W,
                            const float* __restrict__ rel_emb,
                            const int* __restrict__ ksrc, const int* __restrict__ kdst,
                            const int* __restrict__ krel,
                            const int* __restrict__ urow, const int* __restrict__ ucol,
                            const float* __restrict__ uval) {
    int b = blockIdx.x;
    int tid = threadIdx.x;  // 256
    int lane = tid & 31;
    if (b < GEMM_BLOCKS) {
        __shared__ float sWt[DIM][DIM];   // sWt[k][o] = W[o][k]
        for (int idx = tid; idx < DIM * DIM; idx += 256) {
            int o = idx >> 6, k = idx & 63;
            sWt[k][o] = W[idx];
        }
        __syncthreads();
        int row = b * 256 + tid;
        if (row >= NE) return;
        const float4* xp = reinterpret_cast<const float4*>(x + (size_t)row * DIM);
        unsigned long long acc[32];
#pragma unroll
        for (int m = 0; m < 32; m++) acc[m] = 0ull;
#pragma unroll 4
        for (int kc = 0; kc < 16; kc++) {
            float4 xq = __ldg(xp + kc);
#pragma unroll
            for (int j = 0; j < 4; j++) {
                float xv = (j == 0) ? xq.x : (j == 1) ? xq.y : (j == 2) ? xq.z : xq.w;
                unsigned long long xx = pack2(xv, xv);
                const float4* wrow = reinterpret_cast<const float4*>(sWt[kc * 4 + j]);
#pragma unroll
                for (int o4 = 0; o4 < 16; o4++) {
                    float4 w = wrow[o4];
                    fma2(acc[2 * o4],     xx, pack2(w.x, w.y));
                    fma2(acc[2 * o4 + 1], xx, pack2(w.z, w.w));
                }
            }
        }
        // convert 64 fp32 -> 64 fp16, store as 8 uint4 (128B)
        uint4* yp = reinterpret_cast<uint4*>(g_yh + (size_t)row * DIM);
#pragma unroll
        for (int j = 0; j < 8; j++) {
            uint4 v;
            unsigned r32[4];
#pragma unroll
            for (int p = 0; p < 4; p++) {
                float a0, a1;
                unpack2(acc[4 * j + p], a0, a1);
                __half2 h = __floats2half2_rn(a0, a1);
                r32[p] = *reinterpret_cast<unsigned*>(&h);
            }
            v.x = r32[0]; v.y = r32[1]; v.z = r32[2]; v.w = r32[3];
            yp[j] = v;
        }
        return;
    }
    b -= GEMM_BLOCKS;
    if (b < CZBLOCKS) {
        if (b == 0) {
            for (int i = tid; i < NREL * DIM; i += 256) {
                float v = rel_emb[i];
                g_gate[i] = 1.0f / (1.0f + __expf(-v));
            }
        }
        float4 z = make_float4(0.f, 0.f, 0.f, 0.f);
        int base = b * 2048 + tid;
#pragma unroll
        for (int j = 0; j < 8; j++) {
            int i = base + j * 256;
            if (i < ZF4_AGGC) {
                reinterpret_cast<float4*>(g_aggC)[i] = z;
            } else if (i < ZF4_TOTC) {
                reinterpret_cast<float4*>(g_agg2C)[i - ZF4_AGGC] = z;
            }
        }
        return;
    }
    b -= CZBLOCKS;
    if (b < CKG_BLOCKS) {
        int e = b * 256 + tid;
        bool live = false;
        int sr = 0, dr = 0;
        if (e < EKG) {
            int d = __ldg(kdst + e);
            int m = g_remapE[d];
            live = (m >= 2);
            if (live) {
                dr = m - 2;
                sr = __ldg(ksrc + e) | (__ldg(krel + e) << 18);
                atomicAdd(&g_degC[dr], 1.0f);
            }
        }
        unsigned m = __ballot_sync(0xffffffffu, live);
        if (!m) return;
        int leader = __ffs(m) - 1;
        int base = 0;
        if (lane == leader) base = atomicAdd(&g_nKG, __popc(m));
        base = __shfl_sync(0xffffffffu, base, leader);
        if (live) {
            int off = base + __popc(m & ((1u << lane) - 1u));
            g_ksr[off] = sr; g_kdst[off] = dr;
        }
        return;
    }
    b -= CKG_BLOCKS;
    {
        // half 0: e in [0, EUI_HALF)           row=user -> B list
        // half 1: e in [EUI_HALF, 2*EUI_HALF)  row=item -> A list
        int half = (b < CUI_BLOCKS) ? 0 : 1;
        int bb = (half == 0) ? b : b - CUI_BLOCKS;
        int e = bb * 256 + tid + half * EUI_HALF;
        bool live = false;
        int pk = 0;
        float vv = 0.f;
        if (e < (half + 1) * EUI_HALF) {
            int row = __ldg(urow + e);
            int m = g_remapN[row];
            live = (m >= 2);
            if (live) {
                pk = (m - 2) | (__ldg(ucol + e) << 14);
                vv = __ldg(uval + e);
            }
        }
        unsigned m = __ballot_sync(0xffffffffu, live);
        if (!m) return;
        int leader = __ffs(m) - 1;
        int base = 0;
        if (lane == leader) base = atomicAdd(half ? &g_nUIA : &g_nUIB, __popc(m));
        base = __shfl_sync(0xffffffffu, base, leader);
        if (live) {
            int off = base + __popc(m & ((1u << lane) - 1u));
            if (half) { g_apk[off] = pk; g_aval[off] = vv; }
            else      { g_bpk[off] = pk; g_bval[off] = vv; }
        }
    }
}

// ---------------- K3: compacted KG edges (fp16 gather) + UI user-gather edges ----------------
__global__ void edgeA_kernel(const float* __restrict__ user_emb) {
    int b = blockIdx.x;
    int tid = threadIdx.x;
    int q = tid & 7;
    if (b < EA_KG_BLOCKS) {
        int n = g_nKG;
        int slot = (b * 256 + tid) >> 3;
        for (; slot < n; slot += (EA_KG_BLOCKS * 256) / 8) {
            int sr = g_ksr[slot], dr = g_kdst[slot];
            int s = sr & 0x3FFFF, r = sr >> 18;
            uint4 hv = __ldg(reinterpret_cast<const uint4*>(g_yh + (size_t)s * DIM) + q);
            const __half2* hp = reinterpret_cast<const __half2*>(&hv);
            float2 f0 = __half22float2(hp[0]);
            float2 f1 = __half22float2(hp[1]);
            float2 f2 = __half22float2(hp[2]);
            float2 f3 = __half22float2(hp[3]);
            const float4* gp = reinterpret_cast<const float4*>(g_gate + r * DIM + q * 8);
            float4 g0 = __ldg(gp);
            float4 g1 = __ldg(gp + 1);
            float* ap = g_aggC + (size_t)dr * DIM + q * 8;
            red_add_v4(ap,     f0.x * g0.x, f0.y * g0.y, f1.x * g0.z, f1.y * g0.w);
            red_add_v4(ap + 4, f2.x * g1.x, f2.y * g1.y, f3.x * g1.z, f3.y * g1.w);
        }
    } else {
        int n = g_nUIA;
        int slot = ((b - EA_KG_BLOCKS) * 256 + tid) >> 3;
        for (; slot < n; slot += (EA_UI_BLOCKS * 256) / 8) {
            int pk = g_apk[slot];
            int rr = pk & 0x3FFF, cc = (int)((unsigned)pk >> 14);
            float w = g_aval[slot];
            const float4* sp = reinterpret_cast<const float4*>(user_emb + (size_t)cc * DIM) + q;
            float4 v0 = __ldg(sp);
            float4 v1 = __ldg(sp + 8);
            float* ap = g_agg2C + (size_t)rr * DIM + q * 4;
            red_add_v4(ap,      w * v0.x, w * v0.y, w * v0.z, w * v0.w);
            red_add_v4(ap + 32, w * v1.x, w * v1.y, w * v1.z, w * v1.w);
        }
    }
}

// ---------------- K4: per-ITEM post (16 lanes/row, float4) ----------------
__global__ void item_post_kernel(const float* __restrict__ ent, const int* __restrict__ i2e) {
    int tid = threadIdx.x;
    int lane = tid & 31;
    int half = lane >> 4;
    int l16 = lane & 15;
    int item = blockIdx.x * 16 + (tid >> 5) * 2 + half;
    if (item >= NI) return;
    int e = __ldg(i2e + item);
    int re = g_remapE[e] - 2;
    float inv = 1.0f / fmaxf(g_degC[re], 1.0f);
    float4 a = *reinterpret_cast<const float4*>(&g_aggC[(size_t)re * DIM + l16 * 4]);
    float4 x0 = __ldg(reinterpret_cast<const float4*>(&ent[(size_t)e * DIM + l16 * 4]));
    float vx = fmaf(a.x, inv, x0.x);
    float vy = fmaf(a.y, inv, x0.y);
    float vz = fmaf(a.z, inv, x0.z);
    float vw = fmaf(a.w, inv, x0.w);
    vx = (vx > 0.f) ? vx : (__expf(vx) - 1.f);
    vy = (vy > 0.f) ? vy : (__expf(vy) - 1.f);
    vz = (vz > 0.f) ? vz : (__expf(vz) - 1.f);
    vw = (vw > 0.f) ? vw : (__expf(vw) - 1.f);
    float ss = vx * vx + vy * vy + vz * vz + vw * vw;
#pragma unroll
    for (int o = 8; o; o >>= 1) ss += __shfl_xor_sync(0xffffffffu, ss, o);
    float scale = 1.0f / fmaxf(sqrtf(ss), 1e-12f);
    float4 out = make_float4(vx * scale, vy * scale, vz * scale, vw * scale);
    *reinterpret_cast<float4*>(&g_itemkg[(size_t)item * DIM + l16 * 4]) = out;
}

// ---------------- K5: compacted UI item-gather edges ----------------
__global__ void edgeB_kernel() {
    int tid = threadIdx.x;
    int q = tid & 7;
    int n = g_nUIB;
    int slot = (blockIdx.x * 256 + tid) >> 3;
    for (; slot < n; slot += (EB_BLOCKS * 256) / 8) {
        int pk = g_bpk[slot];
        int rr = pk & 0x3FFF, cc = (int)((unsigned)pk >> 14);
        float w = g_bval[slot];
        const float4* sp = reinterpret_cast<const float4*>(g_itemkg + (size_t)(cc - NU) * DIM) + q;
        float4 v0 = __ldg(sp);
        float4 v1 = __ldg(sp + 8);
        float* ap = g_agg2C + (size_t)rr * DIM + q * 4;
        red_add_v4(ap,      w * v0.x, w * v0.y, w * v0.z, w * v0.w);
        red_add_v4(ap + 32, w * v1.x, w * v1.y, w * v1.z, w * v1.w);
    }
}

// ---------------- K6: fused intent + queries + remapE/counter cleanup ----------------
__global__ void query_kernel(const int* __restrict__ qu, const int* __restrict__ qi,
                             const int* __restrict__ qn,
                             const float* __restrict__ user_emb,
                             const float* __restrict__ router_w,
                             const float* __restrict__ router_b,
                             const float* __restrict__ iw,
                             const float* __restrict__ rel_emb,
                             float* __restrict__ out) {
    if (blockIdx.x >= QK_BLOCKS) {
        // cleanup blocks: zero remapE + counters (query blocks never touch remapE)
        int t = (blockIdx.x - QK_BLOCKS) * 256 + threadIdx.x;
        if (t == 0) { g_nKG = 0; g_nUIA = 0; g_nUIB = 0; g_nLiveE = 0; g_nLiveN = 0; }
        if (t < QCLEAN_I4)
            reinterpret_cast<int4*>(g_remapE)[t] = make_int4(0, 0, 0, 0);
        return;
    }
    __shared__ float s_intent[2 * DIM];
    __shared__ float s_sw[2][NREL];
    int tid = threadIdx.x;  // 256
    if (tid < 2) {
        float m = -1e30f;
#pragma unroll
        for (int k = 0; k < NREL; k++) m = fmaxf(m, __ldg(iw + tid * NREL + k));
        float s = 0.f;
#pragma unroll
        for (int k = 0; k < NREL; k++) {
            float e = __expf(__ldg(iw + tid * NREL + k) - m);
            s_sw[tid][k] = e; s += e;
        }
        float inv = 1.0f / s;
#pragma unroll
        for (int k = 0; k < NREL; k++) s_sw[tid][k] *= inv;
    }
    __syncthreads();
    if (tid < 64) {
#pragma unroll
        for (int intent = 0; intent < 2; intent++) {
            float acc = 0.f;
#pragma unroll
            for (int k = 0; k < NREL; k++) acc += s_sw[intent][k] * __ldg(rel_emb + k * DIM + tid);
            s_intent[intent * DIM + tid] = acc;
        }
    }
    __syncthreads();

    int warp = (blockIdx.x * blockDim.x + tid) >> 5;
    int lane = tid & 31;
    if (warp >= NB) return;
    int uu = __ldg(qu + warp), pi = __ldg(qi + warp), ni = __ldg(qn + warp);
    int ru = g_remapN[uu] - 2;
    int rp = g_remapN[NU + pi] - 2;
    int rn = g_remapN[NU + ni] - 2;

    float2 ue0 = __ldg(reinterpret_cast<const float2*>(&user_emb[(size_t)uu * DIM + lane * 2]));
    float2 ag = *reinterpret_cast<const float2*>(&g_agg2C[(size_t)ru * DIM + lane * 2]);
    float fux = 0.5f * (ue0.x + ag.x);
    float fuy = 0.5f * (ue0.y + ag.y);

    float2 rw0 = __ldg(reinterpret_cast<const float2*>(&router_w[lane * 2]));
    float2 rw1 = __ldg(reinterpret_cast<const float2*>(&router_w[DIM + lane * 2]));
    float l0 = fux * rw0.x + fuy * rw0.y;
    float l1 = fux * rw1.x + fuy * rw1.y;
#pragma unroll
    for (int o = 16; o; o >>= 1) {
        l0 += __shfl_xor_sync(0xffffffffu, l0, o);
        l1 += __shfl_xor_sync(0xffffffffu, l1, o);
    }
    l0 += __ldg(router_b + 0);
    l1 += __ldg(router_b + 1);
    float m = fmaxf(l0, l1);
    float e0 = __expf(l0 - m), e1 = __expf(l1 - m);
    float inv = 1.0f / (e0 + e1);
    float p0 = e0 * inv, p1 = e1 * inv;

    float2 i0 = *reinterpret_cast<const float2*>(&s_intent[lane * 2]);
    float2 i1 = *reinterpret_cast<const float2*>(&s_intent[DIM + lane * 2]);
    float uex = fux + p0 * i0.x + p1 * i1.x;
    float uey = fuy + p0 * i0.y + p1 * i1.y;

    float2 ik = *reinterpret_cast<const float2*>(&g_itemkg[(size_t)pi * DIM + lane * 2]);
    float2 a2 = *reinterpret_cast<const float2*>(&g_agg2C[(size_t)rp * DIM + lane * 2]);
    float pos = uex * (1.5f * ik.x + 0.5f * a2.x) + uey * (1.5f * ik.y + 0.5f * a2.y);

    float2 nk = *reinterpret_cast<const float2*>(&g_itemkg[(size_t)ni * DIM + lane * 2]);
    float2 n2 = *reinterpret_cast<const float2*>(&g_agg2C[(size_t)rn * DIM + lane * 2]);
    float neg = uex * (1.5f * nk.x + 0.5f * n2.x) + uey * (1.5f * nk.y + 0.5f * n2.y);

#pragma unroll
    for (int o = 16; o; o >>= 1) {
        pos += __shfl_xor_sync(0xffffffffu, pos, o);
        neg += __shfl_xor_sync(0xffffffffu, neg, o);
    }
    if (lane == 0) {
        out[warp] = pos;
        out[NB + warp] = neg;
    }
}

// ---------------- K7: tail cleanup — zero remapN (read by query) ----------------
__global__ void tail_kernel() {
    int t = blockIdx.x * blockDim.x + threadIdx.x;
    if (t < TAIL_I4)
        reinterpret_cast<int4*>(g_remapN)[t] = make_int4(0, 0, 0, 0);
}

// ---------------- launch ----------------
extern "C" void kernel_launch(void* const* d_in, const int* in_sizes, int n_in,
                              void* d_out, int out_size) {
    const int*   u          = (const int*)d_in[0];
    const int*   it         = (const int*)d_in[1];
    const int*   neg_i      = (const int*)d_in[2];
    const float* user_emb   = (const float*)d_in[3];
    const float* entity_emb = (const float*)d_in[4];
    const float* rel_emb    = (const float*)d_in[5];
    const float* intent_w   = (const float*)d_in[6];
    const float* router_w   = (const float*)d_in[7];
    const float* router_b   = (const float*)d_in[8];
    const float* kg_w       = (const float*)d_in[9];
    const float* ui_vals    = (const float*)d_in[10];
    const int*   item2ent   = (const int*)d_in[11];
    const int*   kg_src     = (const int*)d_in[12];
    const int*   kg_dst     = (const int*)d_in[13];
    const int*   kg_rel     = (const int*)d_in[14];
    const int*   ui_row     = (const int*)d_in[15];
    const int*   ui_col     = (const int*)d_in[16];
    float* out = (float*)d_out;

    set_flags_kernel<<<SF_BLOCKS, 256>>>(item2ent, u, it, neg_i);
    init_kernel<<<INIT_BLOCKS, 256>>>(entity_emb, kg_w, rel_emb,
                                      kg_src, kg_dst, kg_rel,
                                      ui_row, ui_col, ui_vals);
    edgeA_kernel<<<EA_KG_BLOCKS + EA_UI_BLOCKS, 256>>>(user_emb);
    item_post_kernel<<<(NI + 15) / 16, 256>>>(entity_emb, item2ent);
    edgeB_kernel<<<EB_BLOCKS, 256>>>();
    query_kernel<<<QK_BLOCKS + QCLEAN_BLOCKS, 256>>>(u, it, neg_i, user_emb, router_w, router_b,
                                                     intent_w, rel_emb, out);
    tail_kernel<<<TAIL_BLOCKS, 256>>>();
}